// round 2
// baseline (speedup 1.0000x reference)
#include <cuda_runtime.h>
#include <math.h>

#define HH  16
#define SS  2048
#define DD  1024
#define DHD 64
#define HID 4096

// ---------------- scratch (static device allocations are allowed) ----------
__device__ float g_q   [HH * SS * DHD];            // self q (=k=v)   8 MB
__device__ float g_qc  [HH * SS * DHD];            // cross q         8 MB
__device__ float g_kc  [HH * SS * DHD];            // cross k (=v)    8 MB
__device__ float g_scores[67108864];               // H*S*S         256 MB
__device__ float g_tmp [SS * DD];                  // attn/ff out     8 MB
__device__ float g_y1  [SS * DD];
__device__ float g_y2  [SS * DD];
__device__ float g_hid [SS * HID];                 //                32 MB

// ---------------- generic batched SGEMM ------------------------------------
// C[b] = alpha * A[b] (*) B[b] + bias[b], optional relu, optional transB.
// causal_skip: skip tiles entirely above the diagonal (M==N score GEMM).
// causal_k:    truncate K loop at rowStart+BM (P·V with causal-zeroed P).
#define BM 64
#define BN 64
#define BK 16
#define TM 4
#define TN 4

__global__ __launch_bounds__(256)
void gemm_kernel(const float* __restrict__ A, const float* __restrict__ B,
                 const float* __restrict__ bias, float* __restrict__ C,
                 int M, int N, int K,
                 int lda, int ldb, int ldc,
                 long long sA, long long sB, long long sBias, long long sC,
                 float alpha, int transB, int relu, int causal_skip, int causal_k)
{
    int batch = blockIdx.z;
    A += (long long)batch * sA;
    B += (long long)batch * sB;
    C += (long long)batch * sC;
    const float* biasp = bias ? bias + (long long)batch * sBias : nullptr;

    int rowStart = blockIdx.y * BM;
    int colStart = blockIdx.x * BN;
    if (causal_skip && colStart > rowStart + BM - 1) return;
    int kEnd = causal_k ? min(K, rowStart + BM) : K;

    __shared__ float As[BK][BM + 4];
    __shared__ float Bs[BK][BN + 4];

    int tid = threadIdx.x;
    int tx = tid & 15;          // 0..15 -> N
    int ty = tid >> 4;          // 0..15 -> M

    float acc[TM][TN];
#pragma unroll
    for (int i = 0; i < TM; i++)
#pragma unroll
        for (int j = 0; j < TN; j++) acc[i][j] = 0.f;

    for (int k0 = 0; k0 < kEnd; k0 += BK) {
        // A tile: As[k][m] = A[rowStart+m][k0+k]
#pragma unroll
        for (int i = tid; i < BM * BK; i += 256) {
            int m = i / BK, k = i % BK;
            int gm = rowStart + m, gk = k0 + k;
            As[k][m] = (gm < M && gk < K) ? A[(long long)gm * lda + gk] : 0.f;
        }
        if (!transB) {
#pragma unroll
            for (int i = tid; i < BK * BN; i += 256) {
                int k = i / BN, n = i % BN;
                int gk = k0 + k, gn = colStart + n;
                Bs[k][n] = (gk < K && gn < N) ? B[(long long)gk * ldb + gn] : 0.f;
            }
        } else {
#pragma unroll
            for (int i = tid; i < BK * BN; i += 256) {
                int n = i / BK, k = i % BK;     // tid runs over k first: coalesced
                int gk = k0 + k, gn = colStart + n;
                Bs[k][n] = (gk < K && gn < N) ? B[(long long)gn * ldb + gk] : 0.f;
            }
        }
        __syncthreads();

#pragma unroll
        for (int k = 0; k < BK; k++) {
            float a[TM], b[TN];
#pragma unroll
            for (int i = 0; i < TM; i++) a[i] = As[k][ty * TM + i];
#pragma unroll
            for (int j = 0; j < TN; j++) b[j] = Bs[k][tx * TN + j];
#pragma unroll
            for (int i = 0; i < TM; i++)
#pragma unroll
                for (int j = 0; j < TN; j++) acc[i][j] += a[i] * b[j];
        }
        __syncthreads();
    }

#pragma unroll
    for (int i = 0; i < TM; i++) {
        int gm = rowStart + ty * TM + i;
        if (gm >= M) continue;
#pragma unroll
        for (int j = 0; j < TN; j++) {
            int gn = colStart + tx * TN + j;
            if (gn >= N) continue;
            float v = acc[i][j] * alpha + (biasp ? biasp[gn] : 0.f);
            if (relu) v = fmaxf(v, 0.f);
            C[(long long)gm * ldc + gn] = v;
        }
    }
}

// ---------------- row softmax (with causal mask + zero fill) ---------------
__global__ __launch_bounds__(256)
void softmax_kernel(float* __restrict__ x, int causal)
{
    long long row = blockIdx.x;                  // over H*S
    int s = (int)(row % SS);
    float* p = x + row * SS;
    int limit = causal ? (s + 1) : SS;
    int tid = threadIdx.x;
    __shared__ float red[256];

    float m = -3.0e38f;
    for (int t = tid; t < limit; t += 256) m = fmaxf(m, p[t]);
    red[tid] = m; __syncthreads();
    for (int o = 128; o; o >>= 1) { if (tid < o) red[tid] = fmaxf(red[tid], red[tid + o]); __syncthreads(); }
    float rowmax = red[0]; __syncthreads();

    float sum = 0.f;
    for (int t = tid; t < limit; t += 256) {
        float e = __expf(p[t] - rowmax);
        p[t] = e;
        sum += e;
    }
    red[tid] = sum; __syncthreads();
    for (int o = 128; o; o >>= 1) { if (tid < o) red[tid] += red[tid + o]; __syncthreads(); }
    float inv = 1.f / red[0]; __syncthreads();

    for (int t = tid; t < limit; t += 256) p[t] *= inv;
    for (int t = limit + tid; t < SS; t += 256) p[t] = 0.f;   // zero masked region
}

// ---------------- fused residual add + LayerNorm ---------------------------
__global__ __launch_bounds__(256)
void add_ln_kernel(const float* __restrict__ a, const float* __restrict__ b,
                   const float* __restrict__ gamma, const float* __restrict__ beta,
                   float* __restrict__ out)
{
    int row = blockIdx.x;
    int tid = threadIdx.x;
    const float* pa = a + (long long)row * DD;
    const float* pb = b + (long long)row * DD;
    __shared__ float red[256];

    float v[4];
    float s = 0.f;
#pragma unroll
    for (int i = 0; i < 4; i++) {
        int c = tid + i * 256;
        v[i] = pa[c] + pb[c];
        s += v[i];
    }
    red[tid] = s; __syncthreads();
    for (int o = 128; o; o >>= 1) { if (tid < o) red[tid] += red[tid + o]; __syncthreads(); }
    float mu = red[0] * (1.f / DD); __syncthreads();

    float var = 0.f;
#pragma unroll
    for (int i = 0; i < 4; i++) { float d = v[i] - mu; var += d * d; }
    red[tid] = var; __syncthreads();
    for (int o = 128; o; o >>= 1) { if (tid < o) red[tid] += red[tid + o]; __syncthreads(); }
    float rs = rsqrtf(red[0] * (1.f / DD) + 1e-5f); __syncthreads();

#pragma unroll
    for (int i = 0; i < 4; i++) {
        int c = tid + i * 256;
        out[(long long)row * DD + c] = (v[i] - mu) * rs * gamma[c] + beta[c];
    }
}

// ---------------- launch helpers -------------------------------------------
static void launch_gemm(const float* A, const float* B, const float* bias, float* C,
                        int M, int N, int K, int lda, int ldb, int ldc,
                        long long sA, long long sB, long long sBias, long long sC,
                        int batch, float alpha, bool transB, bool relu,
                        bool causalSkip, bool causalK)
{
    dim3 grid((N + BN - 1) / BN, (M + BM - 1) / BM, batch);
    gemm_kernel<<<grid, 256>>>(A, B, bias, C, M, N, K, lda, ldb, ldc,
                               sA, sB, sBias, sC, alpha,
                               (int)transB, (int)relu, (int)causalSkip, (int)causalK);
}

extern "C" void kernel_launch(void* const* d_in, const int* in_sizes, int n_in,
                              void* d_out, int out_size)
{
    const float* y    = (const float*)d_in[0];
    const float* enc  = (const float*)d_in[1];
    const float* Wqs  = (const float*)d_in[2];
    const float* bqs  = (const float*)d_in[3];
    const float* Wqc  = (const float*)d_in[4];
    const float* bqc  = (const float*)d_in[5];
    const float* g1   = (const float*)d_in[6];
    const float* be1  = (const float*)d_in[7];
    const float* g2   = (const float*)d_in[8];
    const float* be2  = (const float*)d_in[9];
    const float* g3   = (const float*)d_in[10];
    const float* be3  = (const float*)d_in[11];
    const float* w1   = (const float*)d_in[12];
    const float* b1   = (const float*)d_in[13];
    const float* w2   = (const float*)d_in[14];
    const float* b2   = (const float*)d_in[15];
    float* out = (float*)d_out;

    float *q, *qc, *kc, *sc, *tmp, *y1, *y2, *hid;
    cudaGetSymbolAddress((void**)&q,   g_q);
    cudaGetSymbolAddress((void**)&qc,  g_qc);
    cudaGetSymbolAddress((void**)&kc,  g_kc);
    cudaGetSymbolAddress((void**)&sc,  g_scores);
    cudaGetSymbolAddress((void**)&tmp, g_tmp);
    cudaGetSymbolAddress((void**)&y1,  g_y1);
    cudaGetSymbolAddress((void**)&y2,  g_y2);
    cudaGetSymbolAddress((void**)&hid, g_hid);

    const long long WST = (long long)DD * DHD;    // per-head W stride
    const long long QST = (long long)SS * DHD;    // per-head q stride
    const long long SCST = (long long)SS * SS;    // per-head score stride
    const float scale = 0.125f;                   // 1/sqrt(64)

    // ---- self attention (q = k = v: one projection) ----
    launch_gemm(y, Wqs, bqs, q, SS, DHD, DD, DD, DHD, DHD,
                0, WST, DHD, QST, HH, 1.f, false, false, false, false);
    // scores = q q^T / 8  (causal tile skip)
    launch_gemm(q, q, nullptr, sc, SS, SS, DHD, DHD, DHD, SS,
                QST, QST, 0, SCST, HH, scale, true, false, true, false);
    softmax_kernel<<<HH * SS, 256>>>(sc, 1);
    // attn_out[s, h*64+e] = sum_t P[h,s,t] q[h,t,e]  (K truncated at diagonal)
    launch_gemm(sc, q, nullptr, tmp, SS, DHD, SS, SS, DHD, DD,
                SCST, QST, 0, DHD, HH, 1.f, false, false, false, true);
    add_ln_kernel<<<SS, 256>>>(y, tmp, g1, be1, y1);

    // ---- cross attention (k = v: one kv projection) ----
    launch_gemm(y1,  Wqc, bqc, qc, SS, DHD, DD, DD, DHD, DHD,
                0, WST, DHD, QST, HH, 1.f, false, false, false, false);
    launch_gemm(enc, Wqc, bqc, kc, SS, DHD, DD, DD, DHD, DHD,
                0, WST, DHD, QST, HH, 1.f, false, false, false, false);
    launch_gemm(qc, kc, nullptr, sc, SS, SS, DHD, DHD, DHD, SS,
                QST, QST, 0, SCST, HH, scale, true, false, false, false);
    softmax_kernel<<<HH * SS, 256>>>(sc, 0);
    launch_gemm(sc, kc, nullptr, tmp, SS, DHD, SS, SS, DHD, DD,
                SCST, QST, 0, DHD, HH, 1.f, false, false, false, false);
    add_ln_kernel<<<SS, 256>>>(y1, tmp, g2, be2, y2);

    // ---- FFN ----
    launch_gemm(y2, w1, b1, hid, SS, HID, DD, DD, HID, HID,
                0, 0, 0, 0, 1, 1.f, false, true, false, false);
    launch_gemm(hid, w2, b2, tmp, SS, DD, HID, HID, DD, DD,
                0, 0, 0, 0, 1, 1.f, false, false, false, false);
    add_ln_kernel<<<SS, 256>>>(y2, tmp, g3, be3, out);
}

// round 3
// speedup vs baseline: 4.0663x; 4.0663x over previous
#include <cuda_runtime.h>
#include <math.h>

#define HH  16
#define SS  2048
#define DD  1024
#define DHD 64
#define HID 4096

// ---------------- scratch (static device allocations allowed) --------------
__device__ float g_q   [HH * SS * DHD];
__device__ float g_qc  [HH * SS * DHD];
__device__ float g_kc  [HH * SS * DHD];
__device__ float g_scores[(long long)HH * SS * SS];   // 256 MB
__device__ float g_tmp [SS * DD];
__device__ float g_y1  [SS * DD];
__device__ float g_y2  [SS * DD];
__device__ float g_hid [SS * HID];

// ---------------- tf32 helpers ---------------------------------------------
__device__ __forceinline__ unsigned f2tf(float f) {
    unsigned u; asm("cvt.rna.tf32.f32 %0, %1;" : "=r"(u) : "f"(f)); return u;
}
__device__ __forceinline__ void mma_tf32(
    float& d0, float& d1, float& d2, float& d3,
    unsigned a0, unsigned a1, unsigned a2, unsigned a3,
    unsigned b0, unsigned b1)
{
    asm volatile(
        "mma.sync.aligned.m16n8k8.row.col.f32.tf32.tf32.f32 "
        "{%0,%1,%2,%3}, {%4,%5,%6,%7}, {%8,%9}, {%0,%1,%2,%3};"
        : "+f"(d0), "+f"(d1), "+f"(d2), "+f"(d3)
        : "r"(a0), "r"(a1), "r"(a2), "r"(a3), "r"(b0), "r"(b1));
}

#define BM 128
#define BK 32
#define SA 36        // BK + 4 floats: row-major tile stride (conflict-free frags)

// ---------------- tensor-core GEMM ------------------------------------------
// C = alpha * A (*) op(B) + bias ; optional relu / causal tile skip / causal K.
// All M,N,K are multiples of the tile sizes for this problem -> no guards.
template<int BN, bool TRANSB>
__global__ __launch_bounds__(256)
void mma_gemm(const float* __restrict__ A, const float* __restrict__ B,
              const float* __restrict__ bias, float* __restrict__ C,
              int K, int lda, int ldb, int ldc,
              long long sA, long long sB, long long sBias, long long sC,
              float alpha, int relu, int causal_skip, int causal_k)
{
    constexpr int SBNT  = BN + 8;                       // non-trans B row stride
    constexpr int NT    = BN / 16;                      // n8 tiles per warp
    constexpr int BITER = TRANSB ? (BN / 32) : ((BK * BN / 4) / 256);
    constexpr int BSZ   = TRANSB ? BN * SA : BK * SBNT;

    __shared__ unsigned As[BM * SA];
    __shared__ unsigned Bs[BSZ];

    const int batch = blockIdx.z;
    A += (long long)batch * sA;
    B += (long long)batch * sB;
    C += (long long)batch * sC;
    const float* biasp = bias ? bias + (long long)batch * sBias : nullptr;

    const int rowStart = blockIdx.y * BM;
    const int colStart = blockIdx.x * BN;
    if (causal_skip && colStart > rowStart) return;
    const int kEnd = causal_k ? (rowStart + BM) : K;
    const int nK = kEnd / BK;

    const int tid  = threadIdx.x;
    const int wid  = tid >> 5, lane = tid & 31;
    const int g    = lane >> 2, tig = lane & 3;
    const int warpM = wid & 3, warpN = wid >> 2;

    // global-load lane mapping
    const int a_m = tid >> 3, a_k = (tid & 7) << 2;
    const float* Agp = A + (long long)(rowStart + a_m) * lda + a_k;

    int b_r, b_c;
    const float* Bgp;
    if (TRANSB) { b_r = tid >> 3; b_c = (tid & 7) << 2;
        Bgp = B + (long long)(colStart + b_r) * ldb + b_c;
    } else { b_r = tid / (BN / 4); b_c = (tid % (BN / 4)) << 2;
        Bgp = B + (long long)b_r * ldb + colStart + b_c;
    }

    float4 ra[4], rb[BITER];

    auto loadA = [&](int k0) {
#pragma unroll
        for (int i = 0; i < 4; i++)
            ra[i] = *(const float4*)(Agp + (long long)(32 * i) * lda + k0);
    };
    auto loadB = [&](int k0) {
        if (TRANSB) {
#pragma unroll
            for (int i = 0; i < BITER; i++)
                rb[i] = *(const float4*)(Bgp + (long long)(32 * i) * ldb + k0);
        } else {
            constexpr int KSTEP = 256 / (BN / 4);
#pragma unroll
            for (int i = 0; i < BITER; i++)
                rb[i] = *(const float4*)(Bgp + (long long)(KSTEP * i + k0) * ldb);
        }
    };
    auto cvst = [&](unsigned* dst, float4 v) {
        uint4 u; u.x = f2tf(v.x); u.y = f2tf(v.y); u.z = f2tf(v.z); u.w = f2tf(v.w);
        *(uint4*)dst = u;
    };
    auto storeTiles = [&]() {
#pragma unroll
        for (int i = 0; i < 4; i++) cvst(&As[(a_m + 32 * i) * SA + a_k], ra[i]);
        if (TRANSB) {
#pragma unroll
            for (int i = 0; i < BITER; i++) cvst(&Bs[(b_r + 32 * i) * SA + b_c], rb[i]);
        } else {
            constexpr int KSTEP = 256 / (BN / 4);
#pragma unroll
            for (int i = 0; i < BITER; i++) cvst(&Bs[(b_r + KSTEP * i) * SBNT + b_c], rb[i]);
        }
    };

    float acc[2][NT][4];
#pragma unroll
    for (int mt = 0; mt < 2; mt++)
#pragma unroll
        for (int nt = 0; nt < NT; nt++)
#pragma unroll
            for (int i = 0; i < 4; i++) acc[mt][nt][i] = 0.f;

    loadA(0); loadB(0);

    for (int kt = 0; kt < nK; kt++) {
        storeTiles();
        __syncthreads();
        if (kt + 1 < nK) { loadA((kt + 1) * BK); loadB((kt + 1) * BK); }

#pragma unroll
        for (int ks = 0; ks < 4; ks++) {
            const int kb = ks * 8;
            unsigned af[2][4];
#pragma unroll
            for (int mt = 0; mt < 2; mt++) {
                const int mr = warpM * 32 + mt * 16;
                af[mt][0] = As[(mr + g)     * SA + kb + tig];
                af[mt][1] = As[(mr + g + 8) * SA + kb + tig];
                af[mt][2] = As[(mr + g)     * SA + kb + tig + 4];
                af[mt][3] = As[(mr + g + 8) * SA + kb + tig + 4];
            }
            unsigned bf[NT][2];
#pragma unroll
            for (int nt = 0; nt < NT; nt++) {
                const int nb = warpN * (BN / 2) + nt * 8;
                if (TRANSB) {
                    bf[nt][0] = Bs[(nb + g) * SA + kb + tig];
                    bf[nt][1] = Bs[(nb + g) * SA + kb + tig + 4];
                } else {
                    bf[nt][0] = Bs[(kb + tig)     * SBNT + nb + g];
                    bf[nt][1] = Bs[(kb + tig + 4) * SBNT + nb + g];
                }
            }
#pragma unroll
            for (int mt = 0; mt < 2; mt++)
#pragma unroll
                for (int nt = 0; nt < NT; nt++)
                    mma_tf32(acc[mt][nt][0], acc[mt][nt][1], acc[mt][nt][2], acc[mt][nt][3],
                             af[mt][0], af[mt][1], af[mt][2], af[mt][3],
                             bf[nt][0], bf[nt][1]);
        }
        __syncthreads();
    }

    // epilogue
#pragma unroll
    for (int mt = 0; mt < 2; mt++) {
        const int r = rowStart + warpM * 32 + mt * 16 + g;
#pragma unroll
        for (int nt = 0; nt < NT; nt++) {
            const int cc = colStart + warpN * (BN / 2) + nt * 8 + 2 * tig;
            const float bb0 = biasp ? biasp[cc]     : 0.f;
            const float bb1 = biasp ? biasp[cc + 1] : 0.f;
            float v0 = acc[mt][nt][0] * alpha + bb0;
            float v1 = acc[mt][nt][1] * alpha + bb1;
            float v2 = acc[mt][nt][2] * alpha + bb0;
            float v3 = acc[mt][nt][3] * alpha + bb1;
            if (relu) { v0 = fmaxf(v0, 0.f); v1 = fmaxf(v1, 0.f);
                        v2 = fmaxf(v2, 0.f); v3 = fmaxf(v3, 0.f); }
            *(float2*)&C[(long long)r       * ldc + cc] = make_float2(v0, v1);
            *(float2*)&C[(long long)(r + 8) * ldc + cc] = make_float2(v2, v3);
        }
    }
}

// ---------------- single-pass register softmax ------------------------------
__global__ __launch_bounds__(256)
void softmax_kernel(float* __restrict__ x, int causal)
{
    const long long row = blockIdx.x;
    const int s = (int)(row & (SS - 1));
    float4* p4 = (float4*)(x + row * SS);
    const int limit = causal ? (s + 1) : SS;
    const int tid = threadIdx.x;
    __shared__ float red[256];

    float4 v[2];
    float m = -3.0e38f;
#pragma unroll
    for (int i = 0; i < 2; i++) {
        v[i] = p4[tid + 256 * i];
        const int c0 = 4 * (tid + 256 * i);
        if (c0 + 0 >= limit) v[i].x = -3.0e38f; else m = fmaxf(m, v[i].x);
        if (c0 + 1 >= limit) v[i].y = -3.0e38f; else m = fmaxf(m, v[i].y);
        if (c0 + 2 >= limit) v[i].z = -3.0e38f; else m = fmaxf(m, v[i].z);
        if (c0 + 3 >= limit) v[i].w = -3.0e38f; else m = fmaxf(m, v[i].w);
    }
    red[tid] = m; __syncthreads();
    for (int o = 128; o; o >>= 1) { if (tid < o) red[tid] = fmaxf(red[tid], red[tid + o]); __syncthreads(); }
    const float rowmax = red[0]; __syncthreads();

    float sum = 0.f;
#pragma unroll
    for (int i = 0; i < 2; i++) {
        v[i].x = __expf(v[i].x - rowmax); sum += v[i].x;
        v[i].y = __expf(v[i].y - rowmax); sum += v[i].y;
        v[i].z = __expf(v[i].z - rowmax); sum += v[i].z;
        v[i].w = __expf(v[i].w - rowmax); sum += v[i].w;
    }
    red[tid] = sum; __syncthreads();
    for (int o = 128; o; o >>= 1) { if (tid < o) red[tid] += red[tid + o]; __syncthreads(); }
    const float inv = 1.f / red[0];

#pragma unroll
    for (int i = 0; i < 2; i++) {
        v[i].x *= inv; v[i].y *= inv; v[i].z *= inv; v[i].w *= inv;
        p4[tid + 256 * i] = v[i];
    }
}

// ---------------- fused residual add + LayerNorm ----------------------------
__global__ __launch_bounds__(256)
void add_ln_kernel(const float* __restrict__ a, const float* __restrict__ b,
                   const float* __restrict__ gamma, const float* __restrict__ beta,
                   float* __restrict__ out)
{
    const int row = blockIdx.x;
    const int tid = threadIdx.x;
    const float* pa = a + (long long)row * DD;
    const float* pb = b + (long long)row * DD;
    __shared__ float red[256];

    float v[4];
    float s = 0.f;
#pragma unroll
    for (int i = 0; i < 4; i++) {
        const int c = tid + i * 256;
        v[i] = pa[c] + pb[c];
        s += v[i];
    }
    red[tid] = s; __syncthreads();
    for (int o = 128; o; o >>= 1) { if (tid < o) red[tid] += red[tid + o]; __syncthreads(); }
    const float mu = red[0] * (1.f / DD); __syncthreads();

    float var = 0.f;
#pragma unroll
    for (int i = 0; i < 4; i++) { const float d = v[i] - mu; var += d * d; }
    red[tid] = var; __syncthreads();
    for (int o = 128; o; o >>= 1) { if (tid < o) red[tid] += red[tid + o]; __syncthreads(); }
    const float rs = rsqrtf(red[0] * (1.f / DD) + 1e-5f); __syncthreads();

#pragma unroll
    for (int i = 0; i < 4; i++) {
        const int c = tid + i * 256;
        out[(long long)row * DD + c] = (v[i] - mu) * rs * gamma[c] + beta[c];
    }
}

// ---------------- host-side orchestration -----------------------------------
extern "C" void kernel_launch(void* const* d_in, const int* in_sizes, int n_in,
                              void* d_out, int out_size)
{
    const float* y    = (const float*)d_in[0];
    const float* enc  = (const float*)d_in[1];
    const float* Wqs  = (const float*)d_in[2];
    const float* bqs  = (const float*)d_in[3];
    const float* Wqc  = (const float*)d_in[4];
    const float* bqc  = (const float*)d_in[5];
    const float* g1   = (const float*)d_in[6];
    const float* be1  = (const float*)d_in[7];
    const float* g2   = (const float*)d_in[8];
    const float* be2  = (const float*)d_in[9];
    const float* g3   = (const float*)d_in[10];
    const float* be3  = (const float*)d_in[11];
    const float* w1   = (const float*)d_in[12];
    const float* b1   = (const float*)d_in[13];
    const float* w2   = (const float*)d_in[14];
    const float* b2   = (const float*)d_in[15];
    float* out = (float*)d_out;

    float *q, *qc, *kc, *sc, *tmp, *y1, *y2, *hid;
    cudaGetSymbolAddress((void**)&q,   g_q);
    cudaGetSymbolAddress((void**)&qc,  g_qc);
    cudaGetSymbolAddress((void**)&kc,  g_kc);
    cudaGetSymbolAddress((void**)&sc,  g_scores);
    cudaGetSymbolAddress((void**)&tmp, g_tmp);
    cudaGetSymbolAddress((void**)&y1,  g_y1);
    cudaGetSymbolAddress((void**)&y2,  g_y2);
    cudaGetSymbolAddress((void**)&hid, g_hid);

    const long long WST  = (long long)DD * DHD;
    const long long QST  = (long long)SS * DHD;
    const long long SCST = (long long)SS * SS;
    const float scale = 0.125f;   // 1/sqrt(64)

    // ---- self attention (q = k = v) ----
    mma_gemm<64, false><<<dim3(1, SS / BM, HH), 256>>>(
        y, Wqs, bqs, q, DD, DD, DHD, DHD, 0, WST, DHD, QST, 1.f, 0, 0, 0);
    mma_gemm<128, true><<<dim3(SS / 128, SS / BM, HH), 256>>>(
        q, q, nullptr, sc, DHD, DHD, DHD, SS, QST, QST, 0, SCST, scale, 0, 1, 0);
    softmax_kernel<<<HH * SS, 256>>>(sc, 1);
    mma_gemm<64, false><<<dim3(1, SS / BM, HH), 256>>>(
        sc, q, nullptr, tmp, SS, SS, DHD, DD, SCST, QST, 0, DHD, 1.f, 0, 0, 1);
    add_ln_kernel<<<SS, 256>>>(y, tmp, g1, be1, y1);

    // ---- cross attention (k = v) ----
    mma_gemm<64, false><<<dim3(1, SS / BM, HH), 256>>>(
        y1, Wqc, bqc, qc, DD, DD, DHD, DHD, 0, WST, DHD, QST, 1.f, 0, 0, 0);
    mma_gemm<64, false><<<dim3(1, SS / BM, HH), 256>>>(
        enc, Wqc, bqc, kc, DD, DD, DHD, DHD, 0, WST, DHD, QST, 1.f, 0, 0, 0);
    mma_gemm<128, true><<<dim3(SS / 128, SS / BM, HH), 256>>>(
        qc, kc, nullptr, sc, DHD, DHD, DHD, SS, QST, QST, 0, SCST, scale, 0, 0, 0);
    softmax_kernel<<<HH * SS, 256>>>(sc, 0);
    mma_gemm<64, false><<<dim3(1, SS / BM, HH), 256>>>(
        sc, kc, nullptr, tmp, SS, SS, DHD, DD, SCST, QST, 0, DHD, 1.f, 0, 0, 0);
    add_ln_kernel<<<SS, 256>>>(y1, tmp, g2, be2, y2);

    // ---- FFN ----
    mma_gemm<128, false><<<dim3(HID / 128, SS / BM, 1), 256>>>(
        y2, w1, b1, hid, DD, DD, HID, HID, 0, 0, 0, 0, 1.f, 1, 0, 0);
    mma_gemm<128, false><<<dim3(DD / 128, SS / BM, 1), 256>>>(
        hid, w2, b2, tmp, HID, HID, DD, DD, 0, 0, 0, 0, 1.f, 0, 0, 0);
    add_ln_kernel<<<SS, 256>>>(y2, tmp, g3, be3, out);
}

// round 4
// speedup vs baseline: 4.7711x; 1.1733x over previous
#include <cuda_runtime.h>
#include <math.h>

#define HH  16
#define SS  2048
#define DD  1024
#define DHD 64
#define HID 4096

// ---------------- scratch ----------------------------------------------------
__device__ float g_q   [HH * SS * DHD];
__device__ float g_qc  [HH * SS * DHD];
__device__ float g_kc  [HH * SS * DHD];
__device__ float g_tmp [SS * DD];
__device__ float g_y1  [SS * DD];
__device__ float g_y2  [SS * DD];
__device__ float g_hid [SS * HID];

// ---------------- tf32 helpers ----------------------------------------------
__device__ __forceinline__ unsigned f2tf(float f) {
    unsigned u; asm("cvt.rna.tf32.f32 %0, %1;" : "=r"(u) : "f"(f)); return u;
}
__device__ __forceinline__ void mma_tf32(
    float& d0, float& d1, float& d2, float& d3,
    unsigned a0, unsigned a1, unsigned a2, unsigned a3,
    unsigned b0, unsigned b1)
{
    asm volatile(
        "mma.sync.aligned.m16n8k8.row.col.f32.tf32.tf32.f32 "
        "{%0,%1,%2,%3}, {%4,%5,%6,%7}, {%8,%9}, {%0,%1,%2,%3};"
        : "+f"(d0), "+f"(d1), "+f"(d2), "+f"(d3)
        : "r"(a0), "r"(a1), "r"(a2), "r"(a3), "r"(b0), "r"(b1));
}

// ======================= generic tensor-core GEMM ===========================
#define BM 128
#define BK 32
#define SA 36

template<int BN, bool TRANSB>
__global__ __launch_bounds__(256)
void mma_gemm(const float* __restrict__ A, const float* __restrict__ B,
              const float* __restrict__ bias, float* __restrict__ C,
              int K, int lda, int ldb, int ldc,
              long long sA, long long sB, long long sBias, long long sC,
              float alpha, int relu)
{
    constexpr int SBNT  = BN + 8;
    constexpr int NT    = BN / 16;
    constexpr int BITER = TRANSB ? (BN / 32) : ((BK * BN / 4) / 256);
    constexpr int BSZ   = TRANSB ? BN * SA : BK * SBNT;

    __shared__ unsigned As[BM * SA];
    __shared__ unsigned Bs[BSZ];

    const int batch = blockIdx.z;
    A += (long long)batch * sA;
    B += (long long)batch * sB;
    C += (long long)batch * sC;
    const float* biasp = bias ? bias + (long long)batch * sBias : nullptr;

    const int rowStart = blockIdx.y * BM;
    const int colStart = blockIdx.x * BN;
    const int nK = K / BK;

    const int tid  = threadIdx.x;
    const int wid  = tid >> 5, lane = tid & 31;
    const int g    = lane >> 2, tig = lane & 3;
    const int warpM = wid & 3, warpN = wid >> 2;

    const int a_m = tid >> 3, a_k = (tid & 7) << 2;
    const float* Agp = A + (long long)(rowStart + a_m) * lda + a_k;

    int b_r, b_c;
    const float* Bgp;
    if (TRANSB) { b_r = tid >> 3; b_c = (tid & 7) << 2;
        Bgp = B + (long long)(colStart + b_r) * ldb + b_c;
    } else { b_r = tid / (BN / 4); b_c = (tid % (BN / 4)) << 2;
        Bgp = B + (long long)b_r * ldb + colStart + b_c;
    }

    float4 ra[4], rb[BITER];

    auto loadA = [&](int k0) {
#pragma unroll
        for (int i = 0; i < 4; i++)
            ra[i] = *(const float4*)(Agp + (long long)(32 * i) * lda + k0);
    };
    auto loadB = [&](int k0) {
        if (TRANSB) {
#pragma unroll
            for (int i = 0; i < BITER; i++)
                rb[i] = *(const float4*)(Bgp + (long long)(32 * i) * ldb + k0);
        } else {
            constexpr int KSTEP = 256 / (BN / 4);
#pragma unroll
            for (int i = 0; i < BITER; i++)
                rb[i] = *(const float4*)(Bgp + (long long)(KSTEP * i + k0) * ldb);
        }
    };
    auto cvst = [&](unsigned* dst, float4 v) {
        uint4 u; u.x = f2tf(v.x); u.y = f2tf(v.y); u.z = f2tf(v.z); u.w = f2tf(v.w);
        *(uint4*)dst = u;
    };
    auto storeTiles = [&]() {
#pragma unroll
        for (int i = 0; i < 4; i++) cvst(&As[(a_m + 32 * i) * SA + a_k], ra[i]);
        if (TRANSB) {
#pragma unroll
            for (int i = 0; i < BITER; i++) cvst(&Bs[(b_r + 32 * i) * SA + b_c], rb[i]);
        } else {
            constexpr int KSTEP = 256 / (BN / 4);
#pragma unroll
            for (int i = 0; i < BITER; i++) cvst(&Bs[(b_r + KSTEP * i) * SBNT + b_c], rb[i]);
        }
    };

    float acc[2][NT][4];
#pragma unroll
    for (int mt = 0; mt < 2; mt++)
#pragma unroll
        for (int nt = 0; nt < NT; nt++)
#pragma unroll
            for (int i = 0; i < 4; i++) acc[mt][nt][i] = 0.f;

    loadA(0); loadB(0);

    for (int kt = 0; kt < nK; kt++) {
        storeTiles();
        __syncthreads();
        if (kt + 1 < nK) { loadA((kt + 1) * BK); loadB((kt + 1) * BK); }

#pragma unroll
        for (int ks = 0; ks < 4; ks++) {
            const int kb = ks * 8;
            unsigned af[2][4];
#pragma unroll
            for (int mt = 0; mt < 2; mt++) {
                const int mr = warpM * 32 + mt * 16;
                af[mt][0] = As[(mr + g)     * SA + kb + tig];
                af[mt][1] = As[(mr + g + 8) * SA + kb + tig];
                af[mt][2] = As[(mr + g)     * SA + kb + tig + 4];
                af[mt][3] = As[(mr + g + 8) * SA + kb + tig + 4];
            }
            unsigned bf[NT][2];
#pragma unroll
            for (int nt = 0; nt < NT; nt++) {
                const int nb = warpN * (BN / 2) + nt * 8;
                if (TRANSB) {
                    bf[nt][0] = Bs[(nb + g) * SA + kb + tig];
                    bf[nt][1] = Bs[(nb + g) * SA + kb + tig + 4];
                } else {
                    bf[nt][0] = Bs[(kb + tig)     * SBNT + nb + g];
                    bf[nt][1] = Bs[(kb + tig + 4) * SBNT + nb + g];
                }
            }
#pragma unroll
            for (int mt = 0; mt < 2; mt++)
#pragma unroll
                for (int nt = 0; nt < NT; nt++)
                    mma_tf32(acc[mt][nt][0], acc[mt][nt][1], acc[mt][nt][2], acc[mt][nt][3],
                             af[mt][0], af[mt][1], af[mt][2], af[mt][3],
                             bf[nt][0], bf[nt][1]);
        }
        __syncthreads();
    }

#pragma unroll
    for (int mt = 0; mt < 2; mt++) {
        const int r = rowStart + warpM * 32 + mt * 16 + g;
#pragma unroll
        for (int nt = 0; nt < NT; nt++) {
            const int cc = colStart + warpN * (BN / 2) + nt * 8 + 2 * tig;
            const float bb0 = biasp ? biasp[cc]     : 0.f;
            const float bb1 = biasp ? biasp[cc + 1] : 0.f;
            float v0 = acc[mt][nt][0] * alpha + bb0;
            float v1 = acc[mt][nt][1] * alpha + bb1;
            float v2 = acc[mt][nt][2] * alpha + bb0;
            float v3 = acc[mt][nt][3] * alpha + bb1;
            if (relu) { v0 = fmaxf(v0, 0.f); v1 = fmaxf(v1, 0.f);
                        v2 = fmaxf(v2, 0.f); v3 = fmaxf(v3, 0.f); }
            *(float2*)&C[(long long)r       * ldc + cc] = make_float2(v0, v1);
            *(float2*)&C[(long long)(r + 8) * ldc + cc] = make_float2(v2, v3);
        }
    }
}

// ======================= fused flash attention ==============================
// Block: 128 query rows x 1 head. 8 warps, each owns 16 full rows.
// KV tile = 64 rows. kv buffer serves both K and V (k==v in this model).
// Q fragments stay in registers; P goes through smem (tf32).
#define FST 68   // smem row stride in words (conflict-free: 68 mod 32 == 4)

template<bool CAUSAL>
__global__ __launch_bounds__(256)
void flash_kernel(const float* __restrict__ Q, const float* __restrict__ KV,
                  float* __restrict__ O)
{
    extern __shared__ unsigned smem[];
    unsigned* Ks = smem;              // 64  * FST
    unsigned* Ps = smem + 64 * FST;   // 128 * FST

    const int h = blockIdx.y;
    const int rowBlk = CAUSAL ? (gridDim.x - 1 - blockIdx.x) : blockIdx.x;
    const float* Qh = Q  + (long long)h * SS * DHD + (long long)rowBlk * 128 * DHD;
    const float* Kh = KV + (long long)h * SS * DHD;

    const int tid = threadIdx.x, wid = tid >> 5, lane = tid & 31;
    const int g = lane >> 2, tig = lane & 3;
    const int mr = wid * 16;

    // stage Q tile through Ps, pull fragments into registers
    for (int i = tid; i < 128 * 16; i += 256) {
        int r = i >> 4, c4 = (i & 15) << 2;
        float4 v = *(const float4*)(Qh + r * DHD + c4);
        uint4 u; u.x = f2tf(v.x); u.y = f2tf(v.y); u.z = f2tf(v.z); u.w = f2tf(v.w);
        *(uint4*)&Ps[r * FST + c4] = u;
    }
    __syncthreads();
    unsigned qf[8][4];
#pragma unroll
    for (int kb = 0; kb < 8; kb++) {
        qf[kb][0] = Ps[(mr + g)     * FST + kb * 8 + tig];
        qf[kb][1] = Ps[(mr + g + 8) * FST + kb * 8 + tig];
        qf[kb][2] = Ps[(mr + g)     * FST + kb * 8 + tig + 4];
        qf[kb][3] = Ps[(mr + g + 8) * FST + kb * 8 + tig + 4];
    }

    float o[8][4];
#pragma unroll
    for (int nt = 0; nt < 8; nt++)
#pragma unroll
        for (int i = 0; i < 4; i++) o[nt][i] = 0.f;
    float m0 = -1e30f, m1 = -1e30f, l0 = 0.f, l1 = 0.f;

    const int nTiles = CAUSAL ? 2 * (rowBlk + 1) : SS / 64;
    const int r0 = rowBlk * 128 + mr + g;
    const int r1 = r0 + 8;

    for (int t = 0; t < nTiles; t++) {
        __syncthreads();                       // prev iter done with Ks/Ps
        for (int i = tid; i < 64 * 16; i += 256) {
            int r = i >> 4, c4 = (i & 15) << 2;
            float4 v = *(const float4*)(Kh + (long long)(t * 64 + r) * DHD + c4);
            uint4 u; u.x = f2tf(v.x); u.y = f2tf(v.y); u.z = f2tf(v.z); u.w = f2tf(v.w);
            *(uint4*)&Ks[r * FST + c4] = u;
        }
        __syncthreads();

        // S = Q K^T
        float s[8][4];
#pragma unroll
        for (int nt = 0; nt < 8; nt++) { s[nt][0] = s[nt][1] = s[nt][2] = s[nt][3] = 0.f; }
#pragma unroll
        for (int kb = 0; kb < 8; kb++) {
#pragma unroll
            for (int nt = 0; nt < 8; nt++) {
                unsigned b0 = Ks[(nt * 8 + g) * FST + kb * 8 + tig];
                unsigned b1 = Ks[(nt * 8 + g) * FST + kb * 8 + tig + 4];
                mma_tf32(s[nt][0], s[nt][1], s[nt][2], s[nt][3],
                         qf[kb][0], qf[kb][1], qf[kb][2], qf[kb][3], b0, b1);
            }
        }

        // scale + mask + tile max
        const int cb = t * 64;
        float tm0 = -1e30f, tm1 = -1e30f;
#pragma unroll
        for (int nt = 0; nt < 8; nt++) {
            const int c0 = cb + nt * 8 + 2 * tig, c1 = c0 + 1;
            s[nt][0] *= 0.125f; s[nt][1] *= 0.125f;
            s[nt][2] *= 0.125f; s[nt][3] *= 0.125f;
            if (CAUSAL) {
                if (c0 > r0) s[nt][0] = -1e30f;
                if (c1 > r0) s[nt][1] = -1e30f;
                if (c0 > r1) s[nt][2] = -1e30f;
                if (c1 > r1) s[nt][3] = -1e30f;
            }
            tm0 = fmaxf(tm0, fmaxf(s[nt][0], s[nt][1]));
            tm1 = fmaxf(tm1, fmaxf(s[nt][2], s[nt][3]));
        }
        tm0 = fmaxf(tm0, __shfl_xor_sync(0xffffffffu, tm0, 1));
        tm0 = fmaxf(tm0, __shfl_xor_sync(0xffffffffu, tm0, 2));
        tm1 = fmaxf(tm1, __shfl_xor_sync(0xffffffffu, tm1, 1));
        tm1 = fmaxf(tm1, __shfl_xor_sync(0xffffffffu, tm1, 2));

        const float mn0 = fmaxf(m0, tm0), mn1 = fmaxf(m1, tm1);
        const float corr0 = __expf(m0 - mn0), corr1 = __expf(m1 - mn1);
        m0 = mn0; m1 = mn1;

        float rs0 = 0.f, rs1 = 0.f;
#pragma unroll
        for (int nt = 0; nt < 8; nt++) {
            s[nt][0] = __expf(s[nt][0] - mn0); rs0 += s[nt][0];
            s[nt][1] = __expf(s[nt][1] - mn0); rs0 += s[nt][1];
            s[nt][2] = __expf(s[nt][2] - mn1); rs1 += s[nt][2];
            s[nt][3] = __expf(s[nt][3] - mn1); rs1 += s[nt][3];
            uint2 p01 = make_uint2(f2tf(s[nt][0]), f2tf(s[nt][1]));
            uint2 p23 = make_uint2(f2tf(s[nt][2]), f2tf(s[nt][3]));
            *(uint2*)&Ps[(mr + g)     * FST + nt * 8 + 2 * tig] = p01;
            *(uint2*)&Ps[(mr + g + 8) * FST + nt * 8 + 2 * tig] = p23;
        }
        rs0 += __shfl_xor_sync(0xffffffffu, rs0, 1);
        rs0 += __shfl_xor_sync(0xffffffffu, rs0, 2);
        rs1 += __shfl_xor_sync(0xffffffffu, rs1, 1);
        rs1 += __shfl_xor_sync(0xffffffffu, rs1, 2);
        l0 = l0 * corr0 + rs0;
        l1 = l1 * corr1 + rs1;
#pragma unroll
        for (int nt = 0; nt < 8; nt++) {
            o[nt][0] *= corr0; o[nt][1] *= corr0;
            o[nt][2] *= corr1; o[nt][3] *= corr1;
        }
        __syncthreads();                       // P visible to all lanes of warp's rows

        // O += P V   (V == K tile)
#pragma unroll
        for (int kb = 0; kb < 8; kb++) {
            unsigned a0 = Ps[(mr + g)     * FST + kb * 8 + tig];
            unsigned a1 = Ps[(mr + g + 8) * FST + kb * 8 + tig];
            unsigned a2 = Ps[(mr + g)     * FST + kb * 8 + tig + 4];
            unsigned a3 = Ps[(mr + g + 8) * FST + kb * 8 + tig + 4];
#pragma unroll
            for (int nt = 0; nt < 8; nt++) {
                unsigned b0 = Ks[(kb * 8 + tig)     * FST + nt * 8 + g];
                unsigned b1 = Ks[(kb * 8 + tig + 4) * FST + nt * 8 + g];
                mma_tf32(o[nt][0], o[nt][1], o[nt][2], o[nt][3],
                         a0, a1, a2, a3, b0, b1);
            }
        }
    }

    // epilogue: O / l  ->  out[s, h*64 + c]
    const float inv0 = 1.f / l0, inv1 = 1.f / l1;
    float* Oh = O + (long long)(rowBlk * 128) * DD + h * DHD;
#pragma unroll
    for (int nt = 0; nt < 8; nt++) {
        const int c = nt * 8 + 2 * tig;
        *(float2*)&Oh[(long long)(mr + g)     * DD + c] =
            make_float2(o[nt][0] * inv0, o[nt][1] * inv0);
        *(float2*)&Oh[(long long)(mr + g + 8) * DD + c] =
            make_float2(o[nt][2] * inv1, o[nt][3] * inv1);
    }
}

// ---------------- single-pass add + LayerNorm --------------------------------
__global__ __launch_bounds__(256)
void add_ln_kernel(const float* __restrict__ a, const float* __restrict__ b,
                   const float* __restrict__ gamma, const float* __restrict__ beta,
                   float* __restrict__ out)
{
    const int row = blockIdx.x;
    const int tid = threadIdx.x;
    const float* pa = a + (long long)row * DD;
    const float* pb = b + (long long)row * DD;
    __shared__ float red[256];

    float v[4];
    float s = 0.f;
#pragma unroll
    for (int i = 0; i < 4; i++) {
        const int c = tid + i * 256;
        v[i] = pa[c] + pb[c];
        s += v[i];
    }
    red[tid] = s; __syncthreads();
    for (int o = 128; o; o >>= 1) { if (tid < o) red[tid] += red[tid + o]; __syncthreads(); }
    const float mu = red[0] * (1.f / DD); __syncthreads();

    float var = 0.f;
#pragma unroll
    for (int i = 0; i < 4; i++) { const float d = v[i] - mu; var += d * d; }
    red[tid] = var; __syncthreads();
    for (int o = 128; o; o >>= 1) { if (tid < o) red[tid] += red[tid + o]; __syncthreads(); }
    const float rs = rsqrtf(red[0] * (1.f / DD) + 1e-5f); __syncthreads();

#pragma unroll
    for (int i = 0; i < 4; i++) {
        const int c = tid + i * 256;
        out[(long long)row * DD + c] = (v[i] - mu) * rs * gamma[c] + beta[c];
    }
}

// ---------------- orchestration ----------------------------------------------
extern "C" void kernel_launch(void* const* d_in, const int* in_sizes, int n_in,
                              void* d_out, int out_size)
{
    const float* y    = (const float*)d_in[0];
    const float* enc  = (const float*)d_in[1];
    const float* Wqs  = (const float*)d_in[2];
    const float* bqs  = (const float*)d_in[3];
    const float* Wqc  = (const float*)d_in[4];
    const float* bqc  = (const float*)d_in[5];
    const float* g1   = (const float*)d_in[6];
    const float* be1  = (const float*)d_in[7];
    const float* g2   = (const float*)d_in[8];
    const float* be2  = (const float*)d_in[9];
    const float* g3   = (const float*)d_in[10];
    const float* be3  = (const float*)d_in[11];
    const float* w1   = (const float*)d_in[12];
    const float* b1   = (const float*)d_in[13];
    const float* w2   = (const float*)d_in[14];
    const float* b2   = (const float*)d_in[15];
    float* out = (float*)d_out;

    float *q, *qc, *kc, *tmp, *y1, *y2, *hid;
    cudaGetSymbolAddress((void**)&q,   g_q);
    cudaGetSymbolAddress((void**)&qc,  g_qc);
    cudaGetSymbolAddress((void**)&kc,  g_kc);
    cudaGetSymbolAddress((void**)&tmp, g_tmp);
    cudaGetSymbolAddress((void**)&y1,  g_y1);
    cudaGetSymbolAddress((void**)&y2,  g_y2);
    cudaGetSymbolAddress((void**)&hid, g_hid);

    const long long WST = (long long)DD * DHD;
    const long long QST = (long long)SS * DHD;
    const int FSMEM = (64 + 128) * FST * 4;   // 52224 bytes

    cudaFuncSetAttribute(flash_kernel<true>,
                         cudaFuncAttributeMaxDynamicSharedMemorySize, FSMEM);
    cudaFuncSetAttribute(flash_kernel<false>,
                         cudaFuncAttributeMaxDynamicSharedMemorySize, FSMEM);

    // ---- self attention (q = k = v) ----
    mma_gemm<64, false><<<dim3(1, SS / BM, HH), 256>>>(
        y, Wqs, bqs, q, DD, DD, DHD, DHD, 0, WST, DHD, QST, 1.f, 0);
    flash_kernel<true><<<dim3(SS / 128, HH), 256, FSMEM>>>(q, q, tmp);
    add_ln_kernel<<<SS, 256>>>(y, tmp, g1, be1, y1);

    // ---- cross attention (k = v) ----
    mma_gemm<64, false><<<dim3(1, SS / BM, HH), 256>>>(
        y1, Wqc, bqc, qc, DD, DD, DHD, DHD, 0, WST, DHD, QST, 1.f, 0);
    mma_gemm<64, false><<<dim3(1, SS / BM, HH), 256>>>(
        enc, Wqc, bqc, kc, DD, DD, DHD, DHD, 0, WST, DHD, QST, 1.f, 0);
    flash_kernel<false><<<dim3(SS / 128, HH), 256, FSMEM>>>(qc, kc, tmp);
    add_ln_kernel<<<SS, 256>>>(y1, tmp, g2, be2, y2);

    // ---- FFN ----
    mma_gemm<128, false><<<dim3(HID / 128, SS / BM, 1), 256>>>(
        y2, w1, b1, hid, DD, DD, HID, HID, 0, 0, 0, 0, 1.f, 1);
    mma_gemm<128, false><<<dim3(DD / 128, SS / BM, 1), 256>>>(
        hid, w2, b2, tmp, HID, HID, DD, DD, 0, 0, 0, 0, 1.f, 0);
    add_ln_kernel<<<SS, 256>>>(y2, tmp, g3, be3, out);
}

// round 5
// speedup vs baseline: 5.3154x; 1.1141x over previous
#include <cuda_runtime.h>
#include <math.h>

#define HH  16
#define SS  2048
#define DD  1024
#define DHD 64
#define HID 4096

// ---------------- scratch ----------------------------------------------------
__device__ float g_q   [HH * SS * DHD];
__device__ float g_qc  [HH * SS * DHD];
__device__ float g_kc  [HH * SS * DHD];
__device__ float g_tmp [SS * DD];
__device__ float g_y1  [SS * DD];
__device__ float g_y2  [SS * DD];
__device__ float g_hid [SS * HID];

// ---------------- helpers ----------------------------------------------------
__device__ __forceinline__ void mma_tf32(
    float& d0, float& d1, float& d2, float& d3,
    unsigned a0, unsigned a1, unsigned a2, unsigned a3,
    unsigned b0, unsigned b1)
{
    asm volatile(
        "mma.sync.aligned.m16n8k8.row.col.f32.tf32.tf32.f32 "
        "{%0,%1,%2,%3}, {%4,%5,%6,%7}, {%8,%9}, {%0,%1,%2,%3};"
        : "+f"(d0), "+f"(d1), "+f"(d2), "+f"(d3)
        : "r"(a0), "r"(a1), "r"(a2), "r"(a3), "r"(b0), "r"(b1));
}
__device__ __forceinline__ void cp16(float* dst, const float* src) {
    unsigned d = (unsigned)__cvta_generic_to_shared(dst);
    asm volatile("cp.async.cg.shared.global [%0], [%1], 16;" :: "r"(d), "l"(src));
}
#define CP_COMMIT() asm volatile("cp.async.commit_group;")
#define CP_WAIT0()  asm volatile("cp.async.wait_group 0;")

// ======================= cp.async double-buffered GEMM ======================
// C = alpha*A*B + bias, optional relu. Raw fp32 bits fed to tf32 mma.
#define BM 128
#define BK 32
#define SA 36

template<int BN>
__global__ __launch_bounds__(256)
void mma_gemm(const float* __restrict__ A, const float* __restrict__ B,
              const float* __restrict__ bias, float* __restrict__ C,
              int K, int lda, int ldb, int ldc,
              long long sA, long long sB, long long sBias, long long sC,
              float alpha, int relu)
{
    constexpr int SBNT  = BN + 8;
    constexpr int NT    = BN / 16;
    constexpr int BITER = (BK * BN / 4) / 256;
    constexpr int KSTEP = 256 / (BN / 4);
    constexpr int ABUF  = BM * SA;
    constexpr int BBUF  = BK * SBNT;

    extern __shared__ float sm[];
    float* As = sm;               // 2 * ABUF
    float* Bs = sm + 2 * ABUF;    // 2 * BBUF

    const int batch = blockIdx.z;
    A += (long long)batch * sA;
    B += (long long)batch * sB;
    C += (long long)batch * sC;
    const float* biasp = bias ? bias + (long long)batch * sBias : nullptr;

    const int rowStart = blockIdx.y * BM;
    const int colStart = blockIdx.x * BN;
    const int nK = K / BK;

    const int tid  = threadIdx.x;
    const int wid  = tid >> 5, lane = tid & 31;
    const int g    = lane >> 2, tig = lane & 3;
    const int warpM = wid & 3, warpN = wid >> 2;

    const int a_m = tid >> 3, a_k = (tid & 7) << 2;
    const float* Agp = A + (long long)(rowStart + a_m) * lda + a_k;

    const int b_r = tid / (BN / 4), b_c = (tid % (BN / 4)) << 2;
    const float* Bgp = B + (long long)b_r * ldb + colStart + b_c;

    auto issue = [&](int kt) {
        const int k0 = kt * BK;
        float* Ad = As + (kt & 1) * ABUF;
        float* Bd = Bs + (kt & 1) * BBUF;
#pragma unroll
        for (int i = 0; i < 4; i++)
            cp16(Ad + (a_m + 32 * i) * SA + a_k, Agp + (long long)(32 * i) * lda + k0);
#pragma unroll
        for (int i = 0; i < BITER; i++)
            cp16(Bd + (b_r + KSTEP * i) * SBNT + b_c,
                 Bgp + (long long)(KSTEP * i + k0) * ldb);
        CP_COMMIT();
    };

    float acc[2][NT][4];
#pragma unroll
    for (int mt = 0; mt < 2; mt++)
#pragma unroll
        for (int nt = 0; nt < NT; nt++)
#pragma unroll
            for (int i = 0; i < 4; i++) acc[mt][nt][i] = 0.f;

    issue(0);

    for (int kt = 0; kt < nK; kt++) {
        CP_WAIT0();
        __syncthreads();                    // tile kt visible; prev compute done
        if (kt + 1 < nK) issue(kt + 1);

        const float* Ac = As + (kt & 1) * ABUF;
        const float* Bc = Bs + (kt & 1) * BBUF;
#pragma unroll
        for (int ks = 0; ks < 4; ks++) {
            const int kb = ks * 8;
            unsigned af[2][4];
#pragma unroll
            for (int mt = 0; mt < 2; mt++) {
                const int mr = warpM * 32 + mt * 16;
                af[mt][0] = __float_as_uint(Ac[(mr + g)     * SA + kb + tig]);
                af[mt][1] = __float_as_uint(Ac[(mr + g + 8) * SA + kb + tig]);
                af[mt][2] = __float_as_uint(Ac[(mr + g)     * SA + kb + tig + 4]);
                af[mt][3] = __float_as_uint(Ac[(mr + g + 8) * SA + kb + tig + 4]);
            }
            unsigned bf[NT][2];
#pragma unroll
            for (int nt = 0; nt < NT; nt++) {
                const int nb = warpN * (BN / 2) + nt * 8;
                bf[nt][0] = __float_as_uint(Bc[(kb + tig)     * SBNT + nb + g]);
                bf[nt][1] = __float_as_uint(Bc[(kb + tig + 4) * SBNT + nb + g]);
            }
#pragma unroll
            for (int mt = 0; mt < 2; mt++)
#pragma unroll
                for (int nt = 0; nt < NT; nt++)
                    mma_tf32(acc[mt][nt][0], acc[mt][nt][1], acc[mt][nt][2], acc[mt][nt][3],
                             af[mt][0], af[mt][1], af[mt][2], af[mt][3],
                             bf[nt][0], bf[nt][1]);
        }
        __syncthreads();                    // compute done before buffer reuse
    }

#pragma unroll
    for (int mt = 0; mt < 2; mt++) {
        const int r = rowStart + warpM * 32 + mt * 16 + g;
#pragma unroll
        for (int nt = 0; nt < NT; nt++) {
            const int cc = colStart + warpN * (BN / 2) + nt * 8 + 2 * tig;
            const float bb0 = biasp ? biasp[cc]     : 0.f;
            const float bb1 = biasp ? biasp[cc + 1] : 0.f;
            float v0 = acc[mt][nt][0] * alpha + bb0;
            float v1 = acc[mt][nt][1] * alpha + bb1;
            float v2 = acc[mt][nt][2] * alpha + bb0;
            float v3 = acc[mt][nt][3] * alpha + bb1;
            if (relu) { v0 = fmaxf(v0, 0.f); v1 = fmaxf(v1, 0.f);
                        v2 = fmaxf(v2, 0.f); v3 = fmaxf(v3, 0.f); }
            *(float2*)&C[(long long)r       * ldc + cc] = make_float2(v0, v1);
            *(float2*)&C[(long long)(r + 8) * ldc + cc] = make_float2(v2, v3);
        }
    }
}

// ======================= fused flash attention ==============================
// 128 query rows x 1 head per block, 8 warps x 16 rows. 64-row KV tiles,
// cp.async double-buffered. K tile serves both K and V (k==v). Raw-bit tf32.
#define FST 68

template<bool CAUSAL>
__global__ __launch_bounds__(256)
void flash_kernel(const float* __restrict__ Q, const float* __restrict__ KV,
                  float* __restrict__ O)
{
    extern __shared__ float sm[];
    float* Ks = sm;                  // 2 * 64 * FST
    float* Ps = sm + 2 * 64 * FST;   // 128 * FST

    const int h = blockIdx.y;
    const int rowBlk = CAUSAL ? (gridDim.x - 1 - blockIdx.x) : blockIdx.x;
    const float* Qh = Q  + (long long)h * SS * DHD + (long long)rowBlk * 128 * DHD;
    const float* Kh = KV + (long long)h * SS * DHD;

    const int tid = threadIdx.x, wid = tid >> 5, lane = tid & 31;
    const int g = lane >> 2, tig = lane & 3;
    const int mr = wid * 16;

    const int k_r = tid >> 2, k_c = (tid & 3) << 4;   // 64 rows x 4 float4s

    auto issueK = [&](int t) {
        float* Kd = Ks + (t & 1) * 64 * FST;
        const float* src = Kh + (long long)(t * 64 + k_r) * DHD + k_c;
#pragma unroll
        for (int i = 0; i < 4; i++)
            cp16(Kd + k_r * FST + k_c + 4 * i, src + 4 * i);
        CP_COMMIT();
    };

    // stage Q tile (raw) through Ps, pull fragments into registers
    for (int i = tid; i < 128 * 16; i += 256) {
        int r = i >> 4, c4 = (i & 15) << 2;
        *(float4*)&Ps[r * FST + c4] = *(const float4*)(Qh + r * DHD + c4);
    }
    issueK(0);
    __syncthreads();
    unsigned qf[8][4];
#pragma unroll
    for (int kb = 0; kb < 8; kb++) {
        qf[kb][0] = __float_as_uint(Ps[(mr + g)     * FST + kb * 8 + tig]);
        qf[kb][1] = __float_as_uint(Ps[(mr + g + 8) * FST + kb * 8 + tig]);
        qf[kb][2] = __float_as_uint(Ps[(mr + g)     * FST + kb * 8 + tig + 4]);
        qf[kb][3] = __float_as_uint(Ps[(mr + g + 8) * FST + kb * 8 + tig + 4]);
    }

    float o[8][4];
#pragma unroll
    for (int nt = 0; nt < 8; nt++)
#pragma unroll
        for (int i = 0; i < 4; i++) o[nt][i] = 0.f;
    float m0 = -1e30f, m1 = -1e30f, l0 = 0.f, l1 = 0.f;

    const int nTiles = CAUSAL ? 2 * (rowBlk + 1) : SS / 64;
    const int r0 = rowBlk * 128 + mr + g;
    const int r1 = r0 + 8;

    for (int t = 0; t < nTiles; t++) {
        CP_WAIT0();
        __syncthreads();                 // K tile t ready; prev iter done with both bufs
        if (t + 1 < nTiles) issueK(t + 1);
        const float* Kc = Ks + (t & 1) * 64 * FST;

        // S = Q K^T
        float s[8][4];
#pragma unroll
        for (int nt = 0; nt < 8; nt++) { s[nt][0] = s[nt][1] = s[nt][2] = s[nt][3] = 0.f; }
#pragma unroll
        for (int kb = 0; kb < 8; kb++) {
#pragma unroll
            for (int nt = 0; nt < 8; nt++) {
                unsigned b0 = __float_as_uint(Kc[(nt * 8 + g) * FST + kb * 8 + tig]);
                unsigned b1 = __float_as_uint(Kc[(nt * 8 + g) * FST + kb * 8 + tig + 4]);
                mma_tf32(s[nt][0], s[nt][1], s[nt][2], s[nt][3],
                         qf[kb][0], qf[kb][1], qf[kb][2], qf[kb][3], b0, b1);
            }
        }

        // scale + mask + online softmax
        const int cb = t * 64;
        float tm0 = -1e30f, tm1 = -1e30f;
#pragma unroll
        for (int nt = 0; nt < 8; nt++) {
            const int c0 = cb + nt * 8 + 2 * tig, c1 = c0 + 1;
            s[nt][0] *= 0.125f; s[nt][1] *= 0.125f;
            s[nt][2] *= 0.125f; s[nt][3] *= 0.125f;
            if (CAUSAL) {
                if (c0 > r0) s[nt][0] = -1e30f;
                if (c1 > r0) s[nt][1] = -1e30f;
                if (c0 > r1) s[nt][2] = -1e30f;
                if (c1 > r1) s[nt][3] = -1e30f;
            }
            tm0 = fmaxf(tm0, fmaxf(s[nt][0], s[nt][1]));
            tm1 = fmaxf(tm1, fmaxf(s[nt][2], s[nt][3]));
        }
        tm0 = fmaxf(tm0, __shfl_xor_sync(0xffffffffu, tm0, 1));
        tm0 = fmaxf(tm0, __shfl_xor_sync(0xffffffffu, tm0, 2));
        tm1 = fmaxf(tm1, __shfl_xor_sync(0xffffffffu, tm1, 1));
        tm1 = fmaxf(tm1, __shfl_xor_sync(0xffffffffu, tm1, 2));

        const float mn0 = fmaxf(m0, tm0), mn1 = fmaxf(m1, tm1);
        const float corr0 = __expf(m0 - mn0), corr1 = __expf(m1 - mn1);
        m0 = mn0; m1 = mn1;

        float rs0 = 0.f, rs1 = 0.f;
#pragma unroll
        for (int nt = 0; nt < 8; nt++) {
            s[nt][0] = __expf(s[nt][0] - mn0); rs0 += s[nt][0];
            s[nt][1] = __expf(s[nt][1] - mn0); rs0 += s[nt][1];
            s[nt][2] = __expf(s[nt][2] - mn1); rs1 += s[nt][2];
            s[nt][3] = __expf(s[nt][3] - mn1); rs1 += s[nt][3];
            *(float2*)&Ps[(mr + g)     * FST + nt * 8 + 2 * tig] = make_float2(s[nt][0], s[nt][1]);
            *(float2*)&Ps[(mr + g + 8) * FST + nt * 8 + 2 * tig] = make_float2(s[nt][2], s[nt][3]);
        }
        rs0 += __shfl_xor_sync(0xffffffffu, rs0, 1);
        rs0 += __shfl_xor_sync(0xffffffffu, rs0, 2);
        rs1 += __shfl_xor_sync(0xffffffffu, rs1, 1);
        rs1 += __shfl_xor_sync(0xffffffffu, rs1, 2);
        l0 = l0 * corr0 + rs0;
        l1 = l1 * corr1 + rs1;
#pragma unroll
        for (int nt = 0; nt < 8; nt++) {
            o[nt][0] *= corr0; o[nt][1] *= corr0;
            o[nt][2] *= corr1; o[nt][3] *= corr1;
        }
        __syncwarp();                    // warp-private Ps rows: warp fence suffices

        // O += P V   (V == K tile)
#pragma unroll
        for (int kb = 0; kb < 8; kb++) {
            unsigned a0 = __float_as_uint(Ps[(mr + g)     * FST + kb * 8 + tig]);
            unsigned a1 = __float_as_uint(Ps[(mr + g + 8) * FST + kb * 8 + tig]);
            unsigned a2 = __float_as_uint(Ps[(mr + g)     * FST + kb * 8 + tig + 4]);
            unsigned a3 = __float_as_uint(Ps[(mr + g + 8) * FST + kb * 8 + tig + 4]);
#pragma unroll
            for (int nt = 0; nt < 8; nt++) {
                unsigned b0 = __float_as_uint(Kc[(kb * 8 + tig)     * FST + nt * 8 + g]);
                unsigned b1 = __float_as_uint(Kc[(kb * 8 + tig + 4) * FST + nt * 8 + g]);
                mma_tf32(o[nt][0], o[nt][1], o[nt][2], o[nt][3],
                         a0, a1, a2, a3, b0, b1);
            }
        }
    }

    const float inv0 = 1.f / l0, inv1 = 1.f / l1;
    float* Oh = O + (long long)(rowBlk * 128) * DD + h * DHD;
#pragma unroll
    for (int nt = 0; nt < 8; nt++) {
        const int c = nt * 8 + 2 * tig;
        *(float2*)&Oh[(long long)(mr + g)     * DD + c] =
            make_float2(o[nt][0] * inv0, o[nt][1] * inv0);
        *(float2*)&Oh[(long long)(mr + g + 8) * DD + c] =
            make_float2(o[nt][2] * inv1, o[nt][3] * inv1);
    }
}

// ---------------- single-pass add + LayerNorm --------------------------------
__global__ __launch_bounds__(256)
void add_ln_kernel(const float* __restrict__ a, const float* __restrict__ b,
                   const float* __restrict__ gamma, const float* __restrict__ beta,
                   float* __restrict__ out)
{
    const int row = blockIdx.x;
    const int tid = threadIdx.x;
    const float* pa = a + (long long)row * DD;
    const float* pb = b + (long long)row * DD;
    __shared__ float red[256];

    float v[4];
    float s = 0.f;
#pragma unroll
    for (int i = 0; i < 4; i++) {
        const int c = tid + i * 256;
        v[i] = pa[c] + pb[c];
        s += v[i];
    }
    red[tid] = s; __syncthreads();
    for (int o = 128; o; o >>= 1) { if (tid < o) red[tid] += red[tid + o]; __syncthreads(); }
    const float mu = red[0] * (1.f / DD); __syncthreads();

    float var = 0.f;
#pragma unroll
    for (int i = 0; i < 4; i++) { const float d = v[i] - mu; var += d * d; }
    red[tid] = var; __syncthreads();
    for (int o = 128; o; o >>= 1) { if (tid < o) red[tid] += red[tid + o]; __syncthreads(); }
    const float rs = rsqrtf(red[0] * (1.f / DD) + 1e-5f); __syncthreads();

#pragma unroll
    for (int i = 0; i < 4; i++) {
        const int c = tid + i * 256;
        out[(long long)row * DD + c] = (v[i] - mu) * rs * gamma[c] + beta[c];
    }
}

// ---------------- orchestration ----------------------------------------------
extern "C" void kernel_launch(void* const* d_in, const int* in_sizes, int n_in,
                              void* d_out, int out_size)
{
    const float* y    = (const float*)d_in[0];
    const float* enc  = (const float*)d_in[1];
    const float* Wqs  = (const float*)d_in[2];
    const float* bqs  = (const float*)d_in[3];
    const float* Wqc  = (const float*)d_in[4];
    const float* bqc  = (const float*)d_in[5];
    const float* g1   = (const float*)d_in[6];
    const float* be1  = (const float*)d_in[7];
    const float* g2   = (const float*)d_in[8];
    const float* be2  = (const float*)d_in[9];
    const float* g3   = (const float*)d_in[10];
    const float* be3  = (const float*)d_in[11];
    const float* w1   = (const float*)d_in[12];
    const float* b1   = (const float*)d_in[13];
    const float* w2   = (const float*)d_in[14];
    const float* b2   = (const float*)d_in[15];
    float* out = (float*)d_out;

    float *q, *qc, *kc, *tmp, *y1, *y2, *hid;
    cudaGetSymbolAddress((void**)&q,   g_q);
    cudaGetSymbolAddress((void**)&qc,  g_qc);
    cudaGetSymbolAddress((void**)&kc,  g_kc);
    cudaGetSymbolAddress((void**)&tmp, g_tmp);
    cudaGetSymbolAddress((void**)&y1,  g_y1);
    cudaGetSymbolAddress((void**)&y2,  g_y2);
    cudaGetSymbolAddress((void**)&hid, g_hid);

    const long long WST = (long long)DD * DHD;
    const long long QST = (long long)SS * DHD;

    const int GS64  = (2 * BM * SA + 2 * BK * (64 + 8))  * 4;   // 55296
    const int GS128 = (2 * BM * SA + 2 * BK * (128 + 8)) * 4;   // 71680
    const int FSMEM = (2 * 64 * FST + 128 * FST) * 4;           // 69632

    cudaFuncSetAttribute(mma_gemm<64>,
                         cudaFuncAttributeMaxDynamicSharedMemorySize, GS64);
    cudaFuncSetAttribute(mma_gemm<128>,
                         cudaFuncAttributeMaxDynamicSharedMemorySize, GS128);
    cudaFuncSetAttribute(flash_kernel<true>,
                         cudaFuncAttributeMaxDynamicSharedMemorySize, FSMEM);
    cudaFuncSetAttribute(flash_kernel<false>,
                         cudaFuncAttributeMaxDynamicSharedMemorySize, FSMEM);

    // ---- self attention (q = k = v) ----
    mma_gemm<64><<<dim3(1, SS / BM, HH), 256, GS64>>>(
        y, Wqs, bqs, q, DD, DD, DHD, DHD, 0, WST, DHD, QST, 1.f, 0);
    flash_kernel<true><<<dim3(SS / 128, HH), 256, FSMEM>>>(q, q, tmp);
    add_ln_kernel<<<SS, 256>>>(y, tmp, g1, be1, y1);

    // ---- cross attention (k = v) ----
    mma_gemm<64><<<dim3(1, SS / BM, HH), 256, GS64>>>(
        y1, Wqc, bqc, qc, DD, DD, DHD, DHD, 0, WST, DHD, QST, 1.f, 0);
    mma_gemm<64><<<dim3(1, SS / BM, HH), 256, GS64>>>(
        enc, Wqc, bqc, kc, DD, DD, DHD, DHD, 0, WST, DHD, QST, 1.f, 0);
    flash_kernel<false><<<dim3(SS / 128, HH), 256, FSMEM>>>(qc, kc, tmp);
    add_ln_kernel<<<SS, 256>>>(y1, tmp, g2, be2, y2);

    // ---- FFN ----
    mma_gemm<128><<<dim3(HID / 128, SS / BM, 1), 256, GS128>>>(
        y2, w1, b1, hid, DD, DD, HID, HID, 0, 0, 0, 0, 1.f, 1);
    mma_gemm<128><<<dim3(DD / 128, SS / BM, 1), 256, GS128>>>(
        hid, w2, b2, tmp, HID, HID, DD, DD, 0, 0, 0, 0, 1.f, 0);
    add_ln_kernel<<<SS, 256>>>(y2, tmp, g3, be3, out);
}